// round 9
// baseline (speedup 1.0000x reference)
#include <cuda_runtime.h>
#include <cuda_bf16.h>
#include <cstdint>

// Problem constants (fixed by setup_inputs)
#define BATCH   16
#define IMG_H   192
#define IMG_W   640
#define HW      (IMG_H * IMG_W)       // 122880
#define XS      240                   // W*3/8
#define XE      400                   // W*5/8
#define PRIOR_W (XE - XS)             // 160
#define NPRIOR  15360                 // (192-96)*160
#define ITERS   200
#define KMED    ((NPRIOR - 1) / 2)    // 7679, torch lower-median index
#define PPT     4                     // points per thread in ransac
#define RBLK    (256 * PPT)           // 1024 points per ransac block
#define MPX     16                    // pixels per thread in mask kernel

// Scratch (static device globals — no allocation)
__device__ float4   g_prior[BATCH * NPRIOR];     // packed prior points
__device__ float    g_prior_y[BATCH * NPRIOR];   // y channel contiguous
__device__ float    g_thr[BATCH];
__device__ float4   g_planes[BATCH * ITERS];     // precomputed hypotheses
__device__ unsigned g_cnt[BATCH * ITERS];        // global inlier counts

// ---------------------------------------------------------------------------
// order-preserving float <-> uint key
// ---------------------------------------------------------------------------
__device__ __forceinline__ unsigned fkey(float f) {
    unsigned u = __float_as_uint(f);
    return (u & 0x80000000u) ? ~u : (u | 0x80000000u);
}
__device__ __forceinline__ float kfloat(unsigned k) {
    unsigned u = (k & 0x80000000u) ? (k ^ 0x80000000u) : ~k;
    return __uint_as_float(u);
}

// ---------------------------------------------------------------------------
// Kernel 1: pack prior crop (full-chip), zero g_cnt
// ---------------------------------------------------------------------------
__global__ void pack_kernel(const float* __restrict__ pt,
                            const float* __restrict__ Kmat) {
    int idx = blockIdx.x * blockDim.x + threadIdx.x;
    if (idx < BATCH * ITERS) g_cnt[idx] = 0u;
    if (idx >= BATCH * NPRIOR) return;
    int b = idx / NPRIOR;
    int n = idx - b * NPRIOR;
    int ys = (int)Kmat[b * 9 + 5];            // K[b,1,2] -> 96
    int r = n / PRIOR_W;
    int c = n - r * PRIOR_W;
    long base = (long)b * 3 * HW + (long)(ys + r) * IMG_W + XS + c;
    float x = pt[base];
    float y = pt[base + HW];
    float z = pt[base + 2 * HW];
    g_prior[idx]   = make_float4(x, y, z, 0.0f);
    g_prior_y[idx] = y;
}

// ---------------------------------------------------------------------------
// Kernel 2: exact lower-medians via 3-pass (11/11/10-bit) radix select,
// with warp-aggregated (__match_any_sync) histogram atomics, then plane
// precompute. One block per batch, 1024 threads.
//   med = median_low(y);  thr = median_low(|med - y|)
// ---------------------------------------------------------------------------
__global__ void __launch_bounds__(1024) median_kernel(const int* __restrict__ sidx) {
    __shared__ float    s_y[NPRIOR];       // 60 KB
    __shared__ unsigned s_hist[2048];      // 8 KB
    __shared__ unsigned s_wsum[32];
    __shared__ unsigned s_woff[32];
    __shared__ unsigned s_prefix;
    __shared__ unsigned s_k;
    __shared__ float    s_med;

    const int b    = blockIdx.x;
    const int tid  = threadIdx.x;
    const int lane = tid & 31;
    const int w    = tid >> 5;

    // load y into shared once
    const float* __restrict__ yv = &g_prior_y[b * NPRIOR];
    #pragma unroll
    for (int n = tid; n < NPRIOR; n += 1024) s_y[n] = yv[n];
    __syncthreads();

    const int SHIFT[3]      = {21, 10, 0};     // digit start bit
    const unsigned DMASK[3] = {0x7FFu, 0x7FFu, 0x3FFu};
    const int HI[3]         = {32, 21, 10};    // resolved-prefix boundary

    for (int mode = 0; mode < 2; mode++) {
        if (tid == 0) { s_prefix = 0u; s_k = KMED; }
        __syncthreads();
        const float med = (mode == 1) ? s_med : 0.0f;

        for (int pass = 0; pass < 3; pass++) {
            const int shift = SHIFT[pass];
            const unsigned dmask = DMASK[pass];
            const int hi = HI[pass];
            s_hist[tid]        = 0u;
            s_hist[tid + 1024] = 0u;
            __syncthreads();
            const unsigned pref = s_prefix;
            const unsigned kk   = s_k;

            // histogram with warp aggregation: one atomic per distinct
            // bin per warp instead of per-element conflict replays
            #pragma unroll
            for (int n = tid; n < NPRIOR; n += 1024) {
                float v = s_y[n];
                if (mode) v = fabsf(med - v);
                unsigned key = fkey(v);
                bool ok = (pass == 0) || ((key >> hi) == (pref >> hi));
                unsigned ball = __ballot_sync(0xFFFFFFFFu, ok);
                if (ok) {
                    unsigned bin = (key >> shift) & dmask;
                    unsigned peers = __match_any_sync(ball, bin);
                    if (lane == (__ffs(peers) - 1))
                        atomicAdd(&s_hist[bin], (unsigned)__popc(peers));
                }
            }
            __syncthreads();

            // parallel exclusive scan over 2048 bins (2 contiguous per thread)
            unsigned h0 = s_hist[2 * tid];
            unsigned h1 = s_hist[2 * tid + 1];
            unsigned local = h0 + h1;
            unsigned incl = local;
            #pragma unroll
            for (int o = 1; o < 32; o <<= 1) {
                unsigned v = __shfl_up_sync(0xFFFFFFFFu, incl, o);
                if (lane >= o) incl += v;
            }
            if (lane == 31) s_wsum[w] = incl;
            __syncthreads();
            if (w == 0) {
                unsigned v = s_wsum[lane];
                unsigned s = v;
                #pragma unroll
                for (int o = 1; o < 32; o <<= 1) {
                    unsigned t = __shfl_up_sync(0xFFFFFFFFu, s, o);
                    if (lane >= o) s += t;
                }
                s_woff[lane] = s - v;   // exclusive warp offset
            }
            __syncthreads();
            unsigned excl = s_woff[w] + (incl - local);
            unsigned cum0 = excl;
            unsigned cum1 = excl + h0;
            if (kk >= cum0 && kk < cum0 + h0) {
                s_prefix = pref | ((unsigned)(2 * tid) << shift);
                s_k = kk - cum0;
            }
            if (kk >= cum1 && kk < cum1 + h1) {
                s_prefix = pref | ((unsigned)(2 * tid + 1) << shift);
                s_k = kk - cum1;
            }
            __syncthreads();
        }
        if (tid == 0) {
            float val = kfloat(s_prefix);
            if (mode == 0) s_med = val;
            else           g_thr[b] = val;
        }
        __syncthreads();
    }

    // --- precompute all 200 hypothesis planes (matches jnp.cross/norm) ---
    if (tid < ITERS) {
        const float4* __restrict__ prior = &g_prior[b * NPRIOR];
        int s0 = sidx[tid * 3 + 0];
        int s1 = sidx[tid * 3 + 1];
        int s2 = sidx[tid * 3 + 2];
        float4 p1 = prior[s0];
        float4 p2 = prior[s1];
        float4 p3 = prior[s2];
        float ax = p2.x - p1.x, ay = p2.y - p1.y, az = p2.z - p1.z;
        float bx = p3.x - p1.x, by = p3.y - p1.y, bz = p3.z - p1.z;
        float nx = ay * bz - az * by;
        float ny = az * bx - ax * bz;
        float nz = ax * by - ay * bx;
        float norm = sqrtf(nx * nx + ny * ny + nz * nz);
        float inv = 1.0f / (norm + 1e-8f);
        nx *= inv; ny *= inv; nz *= inv;
        float d = -(nx * p1.x + ny * p1.y + nz * p1.z);
        g_planes[b * ITERS + tid] = make_float4(nx, ny, nz, d);
    }
}

// ---------------------------------------------------------------------------
// Kernel 3: RANSAC inlier counting, points-in-registers.
// Each block owns RBLK=1024 points (4/thread, registers) and sweeps all 200
// planes from shared (broadcast). Prior is read exactly ONCE per batch.
// grid = (NPRIOR/RBLK, BATCH) = (15, 16), block = 256
// ---------------------------------------------------------------------------
__global__ void __launch_bounds__(256) ransac_kernel() {
    __shared__ float4   s_pl[ITERS];      // 3.2 KB
    __shared__ unsigned s_cnt[ITERS];

    const int b   = blockIdx.y;
    const int tid = threadIdx.x;
    const int n0  = blockIdx.x * RBLK;

    if (tid < ITERS) {
        s_pl[tid]  = g_planes[b * ITERS + tid];
        s_cnt[tid] = 0u;
    }

    // load 4 points into registers (coalesced)
    const float4* __restrict__ prior = &g_prior[b * NPRIOR + n0];
    float px[PPT], py[PPT], pz[PPT];
    #pragma unroll
    for (int k = 0; k < PPT; k++) {
        float4 p = prior[tid + k * 256];
        px[k] = p.x; py[k] = p.y; pz[k] = p.z;
    }
    const float thr = g_thr[b];
    __syncthreads();

    for (int h = 0; h < ITERS; h++) {
        float4 pl = s_pl[h];              // broadcast LDS
        int c = 0;
        #pragma unroll
        for (int k = 0; k < PPT; k++) {
            float dist = fabsf(fmaf(pl.x, px[k],
                               fmaf(pl.y, py[k],
                               fmaf(pl.z, pz[k], pl.w))));
            c += (dist <= thr) ? 1 : 0;
        }
        c = __reduce_add_sync(0xFFFFFFFFu, c);
        if ((tid & 31) == 0) atomicAdd(&s_cnt[h], (unsigned)c);
    }
    __syncthreads();

    if (tid < ITERS) atomicAdd(&g_cnt[b * ITERS + tid], s_cnt[tid]);
}

// ---------------------------------------------------------------------------
// Kernel 4: argmax (per block, cheap) + full-image inlier mask, 16 px/thread
// for MLP. Block = 256 threads covering 4096 px; 30 blocks/batch, 480 total.
// ---------------------------------------------------------------------------
__global__ void __launch_bounds__(256) mask_kernel(const float* __restrict__ pt,
                                                   float* __restrict__ out) {
    __shared__ unsigned s_wmax[8];
    __shared__ float4   s_plane;
    __shared__ float    s_thr;

    const int tid  = threadIdx.x;
    const int lane = tid & 31;
    const int w    = tid >> 5;
    const int blk  = blockIdx.x;
    const int b    = blk / (HW / (256 * MPX));       // 30 blocks per batch
    const int mblk = (blk - b * (HW / (256 * MPX))) * (256 * MPX);

    // parallel argmax over 200 counts with first-index tie-break:
    // key = (count<<8) | (199-i)  -> larger count wins; ties -> smaller i.
    unsigned key = 0;
    if (tid < ITERS)
        key = (g_cnt[b * ITERS + tid] << 8) | (unsigned)(ITERS - 1 - tid);
    #pragma unroll
    for (int o = 16; o > 0; o >>= 1)
        key = max(key, __shfl_xor_sync(0xFFFFFFFFu, key, o));
    if (lane == 0) s_wmax[w] = key;
    __syncthreads();
    if (tid == 0) {
        unsigned k = s_wmax[0];
        #pragma unroll
        for (int i = 1; i < 8; i++) k = max(k, s_wmax[i]);
        int win = ITERS - 1 - (int)(k & 0xFFu);
        float4 pl = g_planes[b * ITERS + win];
        s_plane = pl;
        s_thr   = g_thr[b];
        if (mblk == 0) {                          // plane head, once per batch
            out[b * 4 + 0] = pl.x;
            out[b * 4 + 1] = pl.y;
            out[b * 4 + 2] = pl.z;
            out[b * 4 + 3] = pl.w;
        }
    }
    __syncthreads();

    const float4 pl  = s_plane;
    const float  thr = s_thr;
    const int m = mblk + tid * MPX;               // 16 pixels per thread
    const long base = (long)b * 3 * HW + m;

    float4 xv[MPX / 4], yv[MPX / 4], zv[MPX / 4];
    #pragma unroll
    for (int k = 0; k < MPX / 4; k++) xv[k] = *(const float4*)(pt + base + 4 * k);
    #pragma unroll
    for (int k = 0; k < MPX / 4; k++) yv[k] = *(const float4*)(pt + base + HW + 4 * k);
    #pragma unroll
    for (int k = 0; k < MPX / 4; k++) zv[k] = *(const float4*)(pt + base + 2 * HW + 4 * k);

    float* dst = out + BATCH * 4 + (long)b * HW + m;
    #pragma unroll
    for (int k = 0; k < MPX / 4; k++) {
        float4 r;
        r.x = (fabsf(fmaf(pl.x, xv[k].x, fmaf(pl.y, yv[k].x, fmaf(pl.z, zv[k].x, pl.w)))) <= thr) ? 1.0f : 0.0f;
        r.y = (fabsf(fmaf(pl.x, xv[k].y, fmaf(pl.y, yv[k].y, fmaf(pl.z, zv[k].y, pl.w)))) <= thr) ? 1.0f : 0.0f;
        r.z = (fabsf(fmaf(pl.x, xv[k].z, fmaf(pl.y, yv[k].z, fmaf(pl.z, zv[k].z, pl.w)))) <= thr) ? 1.0f : 0.0f;
        r.w = (fabsf(fmaf(pl.x, xv[k].w, fmaf(pl.y, yv[k].w, fmaf(pl.z, zv[k].w, pl.w)))) <= thr) ? 1.0f : 0.0f;
        *(float4*)(dst + 4 * k) = r;
    }
}

// ---------------------------------------------------------------------------
extern "C" void kernel_launch(void* const* d_in, const int* in_sizes, int n_in,
                              void* d_out, int out_size) {
    const float* pt   = (const float*)d_in[0];   // (B, 3, H*W)
    const float* Kmat = (const float*)d_in[1];   // (B, 3, 3)
    const int*   sidx = (const int*)d_in[2];     // (200, 3)
    float*       out  = (float*)d_out;           // [B*4 planes][B*H*W mask]

    {
        int total = BATCH * NPRIOR;
        pack_kernel<<<(total + 255) / 256, 256>>>(pt, Kmat);
    }
    median_kernel<<<BATCH, 1024>>>(sidx);
    {
        dim3 grid(NPRIOR / RBLK, BATCH);         // (15, 16)
        ransac_kernel<<<grid, 256>>>();
    }
    {
        int blocks = BATCH * HW / (256 * MPX);   // 480
        mask_kernel<<<blocks, 256>>>(pt, out);
    }
}

// round 10
// speedup vs baseline: 1.6968x; 1.6968x over previous
#include <cuda_runtime.h>
#include <cuda_bf16.h>
#include <cstdint>

// Problem constants (fixed by setup_inputs)
#define BATCH   16
#define IMG_H   192
#define IMG_W   640
#define HW      (IMG_H * IMG_W)       // 122880
#define XS      240                   // W*3/8
#define XE      400                   // W*5/8
#define PRIOR_W (XE - XS)             // 160
#define NPRIOR  15360                 // (192-96)*160
#define ITERS   200
#define KMED    ((NPRIOR - 1) / 2)    // 7679, torch lower-median index
#define NH      8                     // hypotheses per ransac block

// Scratch (static device globals — no allocation)
__device__ float4   g_prior[BATCH * NPRIOR];    // packed prior points (x,y,z,0)
__device__ float    g_prior_y[BATCH * NPRIOR];  // y channel contiguous (median)
__device__ float    g_thr[BATCH];
__device__ unsigned g_best[BATCH];              // (count<<8) | (199-iter)

// ---------------------------------------------------------------------------
// order-preserving float <-> uint key
// ---------------------------------------------------------------------------
__device__ __forceinline__ unsigned fkey(float f) {
    unsigned u = __float_as_uint(f);
    return (u & 0x80000000u) ? ~u : (u | 0x80000000u);
}
__device__ __forceinline__ float kfloat(unsigned k) {
    unsigned u = (k & 0x80000000u) ? (k ^ 0x80000000u) : ~k;
    return __uint_as_float(u);
}

// ---------------------------------------------------------------------------
// Kernel 1: pack prior crop into contiguous buffers; init g_best
// ---------------------------------------------------------------------------
__global__ void pack_kernel(const float* __restrict__ pt,
                            const float* __restrict__ Kmat) {
    int idx = blockIdx.x * blockDim.x + threadIdx.x;
    if (idx < BATCH) g_best[idx] = 0u;
    if (idx >= BATCH * NPRIOR) return;
    int b = idx / NPRIOR;
    int n = idx - b * NPRIOR;
    int ys = (int)Kmat[b * 9 + 5];            // K[b,1,2] -> 96
    int r = n / PRIOR_W;
    int c = n - r * PRIOR_W;
    long base = (long)b * 3 * HW + (long)(ys + r) * IMG_W + XS + c;
    float x = pt[base];
    float y = pt[base + HW];
    float z = pt[base + 2 * HW];
    g_prior[idx]   = make_float4(x, y, z, 0.0f);
    g_prior_y[idx] = y;
}

// ---------------------------------------------------------------------------
// Kernel 2: exact lower-median via 3-pass (11/11/10-bit) radix select, twice:
//   med = median_low(y);  thr = median_low(|med - y|)
// One block per batch, 1024 threads. y cached in shared; bin selection via
// parallel block scan. Digit layout: bits [21:32), [10:21), [0:10).
// Pass filter compares all bits >= HI[pass] of the resolved prefix.
// ---------------------------------------------------------------------------
__global__ void __launch_bounds__(1024) median_kernel() {
    __shared__ float    s_y[NPRIOR];       // 60 KB
    __shared__ unsigned s_hist[2048];      // 8 KB
    __shared__ unsigned s_wsum[32];
    __shared__ unsigned s_woff[32];
    __shared__ unsigned s_prefix;
    __shared__ unsigned s_k;
    __shared__ float    s_med;

    const int b    = blockIdx.x;
    const int tid  = threadIdx.x;
    const int lane = tid & 31;
    const int w    = tid >> 5;

    // load y into shared once
    const float* __restrict__ yv = &g_prior_y[b * NPRIOR];
    #pragma unroll
    for (int n = tid; n < NPRIOR; n += 1024) s_y[n] = yv[n];
    __syncthreads();

    const int SHIFT[3]      = {21, 10, 0};     // digit start bit
    const unsigned DMASK[3] = {0x7FFu, 0x7FFu, 0x3FFu};
    const int HI[3]         = {32, 21, 10};    // resolved-prefix boundary

    for (int mode = 0; mode < 2; mode++) {
        if (tid == 0) { s_prefix = 0u; s_k = KMED; }
        __syncthreads();
        const float med = (mode == 1) ? s_med : 0.0f;

        for (int pass = 0; pass < 3; pass++) {
            const int shift = SHIFT[pass];
            const unsigned dmask = DMASK[pass];
            const int hi = HI[pass];
            // zero histogram (2 bins per thread)
            s_hist[tid]        = 0u;
            s_hist[tid + 1024] = 0u;
            __syncthreads();
            const unsigned pref = s_prefix;
            const unsigned kk   = s_k;

            // build histogram over elements matching the resolved prefix
            #pragma unroll
            for (int n = tid; n < NPRIOR; n += 1024) {
                float v = s_y[n];
                if (mode) v = fabsf(med - v);
                unsigned key = fkey(v);
                bool ok = (pass == 0) || ((key >> hi) == (pref >> hi));
                if (ok) atomicAdd(&s_hist[(key >> shift) & dmask], 1u);
            }
            __syncthreads();

            // parallel exclusive scan over 2048 bins (2 contiguous per thread)
            unsigned h0 = s_hist[2 * tid];
            unsigned h1 = s_hist[2 * tid + 1];
            unsigned local = h0 + h1;
            unsigned incl = local;
            #pragma unroll
            for (int o = 1; o < 32; o <<= 1) {
                unsigned v = __shfl_up_sync(0xFFFFFFFFu, incl, o);
                if (lane >= o) incl += v;
            }
            if (lane == 31) s_wsum[w] = incl;
            __syncthreads();
            if (w == 0) {
                unsigned v = s_wsum[lane];
                unsigned s = v;
                #pragma unroll
                for (int o = 1; o < 32; o <<= 1) {
                    unsigned t = __shfl_up_sync(0xFFFFFFFFu, s, o);
                    if (lane >= o) s += t;
                }
                s_woff[lane] = s - v;   // exclusive warp offset
            }
            __syncthreads();
            unsigned excl = s_woff[w] + (incl - local);
            unsigned cum0 = excl;
            unsigned cum1 = excl + h0;
            if (kk >= cum0 && kk < cum0 + h0) {
                s_prefix = pref | ((unsigned)(2 * tid) << shift);
                s_k = kk - cum0;
            }
            if (kk >= cum1 && kk < cum1 + h1) {
                s_prefix = pref | ((unsigned)(2 * tid + 1) << shift);
                s_k = kk - cum1;
            }
            __syncthreads();
        }
        if (tid == 0) {
            float val = kfloat(s_prefix);
            if (mode == 0) s_med = val;
            else           g_thr[b] = val;
        }
        __syncthreads();
    }
}

// ---------------------------------------------------------------------------
// Plane hypothesis (matches jnp.cross / norm / d = -n.p1)
// ---------------------------------------------------------------------------
__device__ __forceinline__ float4 compute_plane(const float4* __restrict__ prior,
                                                const int* __restrict__ sidx,
                                                int i) {
    int s0 = sidx[i * 3 + 0];
    int s1 = sidx[i * 3 + 1];
    int s2 = sidx[i * 3 + 2];
    float4 p1 = prior[s0];
    float4 p2 = prior[s1];
    float4 p3 = prior[s2];
    float ax = p2.x - p1.x, ay = p2.y - p1.y, az = p2.z - p1.z;
    float bx = p3.x - p1.x, by = p3.y - p1.y, bz = p3.z - p1.z;
    float nx = ay * bz - az * by;
    float ny = az * bx - ax * bz;
    float nz = ax * by - ay * bx;
    float norm = sqrtf(nx * nx + ny * ny + nz * nz);
    float inv = 1.0f / (norm + 1e-8f);
    nx *= inv; ny *= inv; nz *= inv;
    float d = -(nx * p1.x + ny * p1.y + nz * p1.z);
    return make_float4(nx, ny, nz, d);
}

// ---------------------------------------------------------------------------
// Kernel 3: RANSAC inlier counting. One block = NH(8) hypotheses, single
// shared streaming pass over the points (loop interchange: 8x fewer loads).
// grid = (25, 16), block = 256
// ---------------------------------------------------------------------------
__global__ void __launch_bounds__(256) ransac_kernel(const int* __restrict__ sidx) {
    __shared__ float4 s_plane[NH];
    __shared__ unsigned s_cnt[NH];

    const int b   = blockIdx.y;
    const int tid = threadIdx.x;
    const int i0  = blockIdx.x * NH;

    const float4* __restrict__ prior = &g_prior[b * NPRIOR];

    if (tid < NH) {
        s_plane[tid] = compute_plane(prior, sidx, i0 + tid);
        s_cnt[tid] = 0u;
    }
    __syncthreads();

    const float thr = g_thr[b];
    float4 pl[NH];
    #pragma unroll
    for (int h = 0; h < NH; h++) pl[h] = s_plane[h];

    int cnt[NH];
    #pragma unroll
    for (int h = 0; h < NH; h++) cnt[h] = 0;

    #pragma unroll 2
    for (int n = tid; n < NPRIOR; n += 256) {
        float4 p = prior[n];
        #pragma unroll
        for (int h = 0; h < NH; h++) {
            float dist = fabsf(fmaf(pl[h].x, p.x,
                               fmaf(pl[h].y, p.y,
                               fmaf(pl[h].z, p.z, pl[h].w))));
            cnt[h] += (dist <= thr) ? 1 : 0;
        }
    }

    #pragma unroll
    for (int h = 0; h < NH; h++) {
        int c = __reduce_add_sync(0xFFFFFFFFu, cnt[h]);
        if ((tid & 31) == 0) atomicAdd(&s_cnt[h], (unsigned)c);
    }
    __syncthreads();

    if (tid < NH) {
        int i = i0 + tid;
        // argmax with first-index tie-break: larger count wins;
        // equal count -> larger (199-i) wins -> smaller i wins.
        unsigned key = (s_cnt[tid] << 8) | (unsigned)(ITERS - 1 - i);
        atomicMax(&g_best[b], key);
    }
}

// ---------------------------------------------------------------------------
// Kernel 4: full-image inlier mask (0.0/1.0), 8 px/thread (two float4 lanes
// of loads in flight), winning plane recomputed per block (finalize fused).
// Block = 256 threads covering 2048 pixels; 60 blocks/batch, 960 total.
// ---------------------------------------------------------------------------
__global__ void __launch_bounds__(256) mask_kernel(const float* __restrict__ pt,
                                                   const int* __restrict__ sidx,
                                                   float* __restrict__ out) {
    __shared__ float4 s_pl;
    __shared__ float  s_thr;

    const int tid  = threadIdx.x;
    const int blk  = blockIdx.x;
    const int b    = blk / (HW / 2048);          // 60 blocks per batch
    const int mblk = (blk - b * (HW / 2048)) * 2048;

    if (tid == 0) {
        unsigned best = g_best[b];
        int i = ITERS - 1 - (int)(best & 0xFFu);
        float4 pl = compute_plane(&g_prior[b * NPRIOR], sidx, i);
        s_pl  = pl;
        s_thr = g_thr[b];
        if (mblk == 0) {                          // write plane head once per batch
            out[b * 4 + 0] = pl.x;
            out[b * 4 + 1] = pl.y;
            out[b * 4 + 2] = pl.z;
            out[b * 4 + 3] = pl.w;
        }
    }
    __syncthreads();

    const float4 pl  = s_pl;
    const float  thr = s_thr;
    const int m = mblk + tid * 8;                 // 8 pixels per thread
    const long base = (long)b * 3 * HW + m;

    float4 x0 = *(const float4*)(pt + base);
    float4 x1 = *(const float4*)(pt + base + 4);
    float4 y0 = *(const float4*)(pt + base + HW);
    float4 y1 = *(const float4*)(pt + base + HW + 4);
    float4 z0 = *(const float4*)(pt + base + 2 * HW);
    float4 z1 = *(const float4*)(pt + base + 2 * HW + 4);

    float4 r0, r1;
    r0.x = (fabsf(fmaf(pl.x, x0.x, fmaf(pl.y, y0.x, fmaf(pl.z, z0.x, pl.w)))) <= thr) ? 1.0f : 0.0f;
    r0.y = (fabsf(fmaf(pl.x, x0.y, fmaf(pl.y, y0.y, fmaf(pl.z, z0.y, pl.w)))) <= thr) ? 1.0f : 0.0f;
    r0.z = (fabsf(fmaf(pl.x, x0.z, fmaf(pl.y, y0.z, fmaf(pl.z, z0.z, pl.w)))) <= thr) ? 1.0f : 0.0f;
    r0.w = (fabsf(fmaf(pl.x, x0.w, fmaf(pl.y, y0.w, fmaf(pl.z, z0.w, pl.w)))) <= thr) ? 1.0f : 0.0f;
    r1.x = (fabsf(fmaf(pl.x, x1.x, fmaf(pl.y, y1.x, fmaf(pl.z, z1.x, pl.w)))) <= thr) ? 1.0f : 0.0f;
    r1.y = (fabsf(fmaf(pl.x, x1.y, fmaf(pl.y, y1.y, fmaf(pl.z, z1.y, pl.w)))) <= thr) ? 1.0f : 0.0f;
    r1.z = (fabsf(fmaf(pl.x, x1.z, fmaf(pl.y, y1.z, fmaf(pl.z, z1.z, pl.w)))) <= thr) ? 1.0f : 0.0f;
    r1.w = (fabsf(fmaf(pl.x, x1.w, fmaf(pl.y, y1.w, fmaf(pl.z, z1.w, pl.w)))) <= thr) ? 1.0f : 0.0f;

    float* dst = out + BATCH * 4 + (long)b * HW + m;
    *(float4*)(dst)     = r0;
    *(float4*)(dst + 4) = r1;
}

// ---------------------------------------------------------------------------
extern "C" void kernel_launch(void* const* d_in, const int* in_sizes, int n_in,
                              void* d_out, int out_size) {
    const float* pt   = (const float*)d_in[0];   // (B, 3, H*W)
    const float* Kmat = (const float*)d_in[1];   // (B, 3, 3)
    const int*   sidx = (const int*)d_in[2];     // (200, 3)
    float*       out  = (float*)d_out;           // [B*4 planes][B*H*W mask]

    {
        int total = BATCH * NPRIOR;
        pack_kernel<<<(total + 255) / 256, 256>>>(pt, Kmat);
    }
    median_kernel<<<BATCH, 1024>>>();
    {
        dim3 grid(ITERS / NH, BATCH);            // (25, 16)
        ransac_kernel<<<grid, 256>>>(sidx);
    }
    {
        int blocks = BATCH * HW / 2048;          // 960
        mask_kernel<<<blocks, 256>>>(pt, sidx, out);
    }
}